// round 1
// baseline (speedup 1.0000x reference)
#include <cuda_runtime.h>
#include <math.h>
#include <stdint.h>

typedef unsigned long long ull;

// ---------------- constants ----------------
#define TT    24          // timesteps per CTA tile (240/24 = 10 tiles)
#define XSTR  28          // smem row stride for [180][TT] tiles (16B aligned, conflict-friendly)
#define KC    20          // K-chunk staged in smem (180 = 9 * 20)
#define NCH   9
#define THR1  192         // fused kernel threads: 3 t-groups x 64 h-lanes

#define SMEM_XS   0
#define SMEM_HS   20160                  // 180*28*4
#define SMEM_WS   40320                  // + 180*28*4
#define SMEM_RA   101760                 // + 20*768*4
#define SMEM_RM   102528                 // + 8*24*4
#define SMEM_RS   102624
#define SMEM1_TOTAL 102720

// ---------------- device scratch (static allocation only) ----------------
__device__ float g_WencP[180 * 180 * 4];     // [k][h][{i,g,o,pad}]
__device__ float g_WdecP[180 * 180 * 4];
__device__ float g_bencP[180 * 4];
__device__ float g_bdecP[180 * 4];
__device__ float g_hdec[88473600];           // [2048][240][180]  (354 MB)
__device__ float g_part[16 * 2048 * 40];     // split-K partial logits

// ---------------- f32x2 helpers (PTX-only pattern) ----------------
__device__ __forceinline__ ull ffma2(ull a, ull b, ull c) {
    ull d;
    asm("fma.rn.f32x2 %0, %1, %2, %3;" : "=l"(d) : "l"(a), "l"(b), "l"(c));
    return d;
}
__device__ __forceinline__ ull packf2(float w) {
    ull d;
    asm("mov.b64 %0, {%1, %1};" : "=l"(d) : "f"(w));
    return d;
}
__device__ __forceinline__ float2 unpackf2(ull v) {
    float2 r;
    asm("mov.b64 {%0, %1}, %2;" : "=f"(r.x), "=f"(r.y) : "l"(v));
    return r;
}
__device__ __forceinline__ float sigmoidf_(float v) { return 1.f / (1.f + expf(-v)); }

// ---------------- kernel P: repack weights k-major, (i,g,o) interleaved ----------------
__global__ void pack_weights(const float* __restrict__ We, const float* __restrict__ bie,
                             const float* __restrict__ bhe, const float* __restrict__ Wd,
                             const float* __restrict__ bid, const float* __restrict__ bhd) {
    int idx = blockIdx.x * blockDim.x + threadIdx.x;
    int stride = gridDim.x * blockDim.x;
    for (int i = idx; i < 180 * 180; i += stride) {
        int k = i / 180, h = i % 180;
        float4 ve, vd;
        ve.x = We[h * 180 + k];           // i-gate row
        ve.y = We[(360 + h) * 180 + k];   // g-gate row
        ve.z = We[(540 + h) * 180 + k];   // o-gate row
        ve.w = 0.f;
        vd.x = Wd[h * 180 + k];
        vd.y = Wd[(360 + h) * 180 + k];
        vd.z = Wd[(540 + h) * 180 + k];
        vd.w = 0.f;
        *(float4*)&g_WencP[(size_t)i * 4] = ve;
        *(float4*)&g_WdecP[(size_t)i * 4] = vd;
    }
    for (int h = idx; h < 180; h += stride) {
        g_bencP[h * 4 + 0] = bie[h] + bhe[h];
        g_bencP[h * 4 + 1] = bie[360 + h] + bhe[360 + h];
        g_bencP[h * 4 + 2] = bie[540 + h] + bhe[540 + h];
        g_bencP[h * 4 + 3] = 0.f;
        g_bdecP[h * 4 + 0] = bid[h] + bhd[h];
        g_bdecP[h * 4 + 1] = bid[360 + h] + bhd[360 + h];
        g_bdecP[h * 4 + 2] = bid[540 + h] + bhd[540 + h];
        g_bdecP[h * 4 + 3] = 0.f;
    }
}

// ---------------- kernel 1: fused enc-GEMM -> softmax -> dec-GEMM -> hdec ----------------
__global__ void __launch_bounds__(THR1, 2) fused_encdec(const float* __restrict__ x) {
    extern __shared__ char smem_raw[];
    float(*Xs)[XSTR] = reinterpret_cast<float(*)[XSTR]>(smem_raw + SMEM_XS);
    float(*Hs)[XSTR] = reinterpret_cast<float(*)[XSTR]>(smem_raw + SMEM_HS);
    float(*Ws)[768]  = reinterpret_cast<float(*)[768]>(smem_raw + SMEM_WS);
    float(*redA)[24] = reinterpret_cast<float(*)[24]>(smem_raw + SMEM_RA);
    float* redM = reinterpret_cast<float*>(smem_raw + SMEM_RM);
    float* redS = reinterpret_cast<float*>(smem_raw + SMEM_RS);

    const int b  = blockIdx.y;
    const int t0 = blockIdx.x * TT;
    const int tid = threadIdx.x;
    const int tx = tid / 64;   // 0..2 : t-group of 8 timesteps
    const int ty = tid % 64;   // h lanes

    // load input tile: Xs[f][t] = x[b][f][t0+t]   (x is [B,180,240] contiguous)
    for (int i = tid; i < 180 * TT; i += THR1) {
        int f = i / TT, t = i % TT;
        Xs[f][t] = x[((size_t)b * 180 + f) * 240 + t0 + t];
    }

    for (int pass = 0; pass < 2; pass++) {
        const float* Wg = pass ? g_WdecP : g_WencP;
        ull acc[3][3][4];
#pragma unroll
        for (int j = 0; j < 3; j++)
#pragma unroll
            for (int g = 0; g < 3; g++)
#pragma unroll
                for (int v = 0; v < 4; v++) acc[j][g][v] = 0ull;

        for (int c = 0; c < NCH; c++) {
            __syncthreads();  // protect Ws reuse; also orders Xs producers (load / softmax)
            // stage W chunk [KC][180][4] -> smem rows padded to 768 floats
            for (int i = tid; i < KC * 720; i += THR1) {
                Ws[i / 720][i % 720] = Wg[(size_t)c * KC * 720 + i];
            }
            __syncthreads();
#pragma unroll 4
            for (int kk = 0; kk < KC; kk++) {
                const int k = c * KC + kk;
                ulonglong2 xa = *(const ulonglong2*)&Xs[k][tx * 8];
                ulonglong2 xb = *(const ulonglong2*)&Xs[k][tx * 8 + 4];
                ull xs0 = xa.x, xs1 = xa.y, xs2 = xb.x, xs3 = xb.y;
#pragma unroll
                for (int j = 0; j < 3; j++) {
                    const float4 w4 = *(const float4*)&Ws[kk][(ty + 64 * j) * 4];
                    ull wi = packf2(w4.x), wg = packf2(w4.y), wo = packf2(w4.z);
                    acc[j][0][0] = ffma2(xs0, wi, acc[j][0][0]);
                    acc[j][0][1] = ffma2(xs1, wi, acc[j][0][1]);
                    acc[j][0][2] = ffma2(xs2, wi, acc[j][0][2]);
                    acc[j][0][3] = ffma2(xs3, wi, acc[j][0][3]);
                    acc[j][1][0] = ffma2(xs0, wg, acc[j][1][0]);
                    acc[j][1][1] = ffma2(xs1, wg, acc[j][1][1]);
                    acc[j][1][2] = ffma2(xs2, wg, acc[j][1][2]);
                    acc[j][1][3] = ffma2(xs3, wg, acc[j][1][3]);
                    acc[j][2][0] = ffma2(xs0, wo, acc[j][2][0]);
                    acc[j][2][1] = ffma2(xs1, wo, acc[j][2][1]);
                    acc[j][2][2] = ffma2(xs2, wo, acc[j][2][2]);
                    acc[j][2][3] = ffma2(xs3, wo, acc[j][2][3]);
                }
            }
        }

        // activations: c = sig(i)*tanh(g); h = sig(o)*tanh(c)
        const float* bp = pass ? g_bdecP : g_bencP;
#pragma unroll
        for (int j = 0; j < 3; j++) {
            int h = ty + 64 * j;
            if (h < 180) {
                float4 bb = *(const float4*)&bp[h * 4];
#pragma unroll
                for (int v = 0; v < 4; v++) {
                    float2 fi = unpackf2(acc[j][0][v]);
                    float2 fg = unpackf2(acc[j][1][v]);
                    float2 fo = unpackf2(acc[j][2][v]);
                    float c0 = sigmoidf_(fi.x + bb.x) * tanhf(fg.x + bb.y);
                    float c1 = sigmoidf_(fi.y + bb.x) * tanhf(fg.y + bb.y);
                    float h0 = sigmoidf_(fo.x + bb.z) * tanhf(c0);
                    float h1 = sigmoidf_(fo.y + bb.z) * tanhf(c1);
                    Hs[h][tx * 8 + 2 * v]     = h0;
                    Hs[h][tx * 8 + 2 * v + 1] = h1;
                }
            }
        }
        __syncthreads();

        if (pass == 0) {
            // softmax over h (180) per column t, result -> Xs (decoder input)
            int col = tid % 24, sl = tid / 24;            // 24 cols x 8 slices = 192
            int h0 = sl * 23, h1 = min(180, h0 + 23);
            float m = -1e30f;
            for (int h = h0; h < h1; h++) m = fmaxf(m, Hs[h][col]);
            redA[sl][col] = m;
            __syncthreads();
            if (sl == 0) {
                float mm = redA[0][col];
#pragma unroll
                for (int s = 1; s < 8; s++) mm = fmaxf(mm, redA[s][col]);
                redM[col] = mm;
            }
            __syncthreads();
            float mm = redM[col];
            float s = 0.f;
            for (int h = h0; h < h1; h++) s += expf(Hs[h][col] - mm);
            redA[sl][col] = s;
            __syncthreads();
            if (sl == 0) {
                float ss = 0.f;
#pragma unroll
                for (int s2 = 0; s2 < 8; s2++) ss += redA[s2][col];
                redS[col] = 1.f / ss;
            }
            __syncthreads();
            float inv = redS[col];
            for (int h = h0; h < h1; h++) Xs[h][col] = expf(Hs[h][col] - mm) * inv;
            // next pass's first __syncthreads() orders these writes vs readers
        } else {
            // write h_dec: g_hdec[b][t0+t][h]
            for (int i = tid; i < 180 * TT; i += THR1) {
                int h = i % 180, t = i / 180;
                g_hdec[((size_t)b * 240 + t0 + t) * 180 + h] = Hs[h][t];
            }
        }
    }
}

// ---------------- kernel C: output GEMM, split-K partials ----------------
// logits_part[ks][b][n] over K-range ks*2700..+2700 ; 64 b per CTA, 40 n
__global__ void __launch_bounds__(256) out_gemm(const float* __restrict__ Wout) {
    __shared__ float Hc[64][62];
    __shared__ float Wc[40][62];
    const int ks = blockIdx.x;        // 0..15
    const int b0 = blockIdx.y * 64;   // 0..31 tiles
    const int k0 = ks * 2700;
    const int tid = threadIdx.x;
    const int bg = tid % 32;          // lane -> b
    const int ng = tid / 32;          // 0..7 -> 5 n each

    ull acc2[2][5];
#pragma unroll
    for (int bi = 0; bi < 2; bi++)
#pragma unroll
        for (int q = 0; q < 5; q++) acc2[bi][q] = 0ull;

    for (int c = 0; c < 45; c++) {
        __syncthreads();
        const int kb = k0 + c * 60;
        for (int i = tid; i < 64 * 60; i += 256) {
            int bb = i / 60, k = i % 60;
            Hc[bb][k] = g_hdec[(size_t)(b0 + bb) * 43200 + kb + k];
        }
        for (int i = tid; i < 40 * 60; i += 256) {
            int n = i / 60, k = i % 60;
            Wc[n][k] = Wout[(size_t)n * 43200 + kb + k];
        }
        __syncthreads();
#pragma unroll 6
        for (int kp = 0; kp < 30; kp++) {
            ull h0 = *(const ull*)&Hc[bg][kp * 2];
            ull h1 = *(const ull*)&Hc[bg + 32][kp * 2];
#pragma unroll
            for (int q = 0; q < 5; q++) {
                ull w = *(const ull*)&Wc[ng * 5 + q][kp * 2];
                acc2[0][q] = ffma2(h0, w, acc2[0][q]);
                acc2[1][q] = ffma2(h1, w, acc2[1][q]);
            }
        }
    }
#pragma unroll
    for (int bi = 0; bi < 2; bi++)
#pragma unroll
        for (int q = 0; q < 5; q++) {
            float2 p = unpackf2(acc2[bi][q]);
            g_part[((size_t)ks * 2048 + b0 + bg + 32 * bi) * 40 + ng * 5 + q] = p.x + p.y;
        }
}

// ---------------- kernel D: reduce split-K + bias + grouped softmax ----------------
__global__ void reduce_softmax(const float* __restrict__ bout, float* __restrict__ out) {
    __shared__ float sm[40];
    const int b = blockIdx.x;
    const int n = threadIdx.x;  // 0..39
    float l = bout[n];
#pragma unroll
    for (int ks = 0; ks < 16; ks++) l += g_part[((size_t)ks * 2048 + b) * 40 + n];
    sm[n] = l;
    __syncthreads();
    const int g0 = (n / 10) * 10;
    float m = sm[g0];
#pragma unroll
    for (int i = 1; i < 10; i++) m = fmaxf(m, sm[g0 + i]);
    float s = 0.f;
#pragma unroll
    for (int i = 0; i < 10; i++) s += expf(sm[g0 + i] - m);
    out[(size_t)b * 40 + n] = expf(l - m) / s;
}

// ---------------- launcher ----------------
extern "C" void kernel_launch(void* const* d_in, const int* in_sizes, int n_in,
                              void* d_out, int out_size) {
    const float* x    = (const float*)d_in[0];
    const float* Wenc = (const float*)d_in[1];
    const float* bie  = (const float*)d_in[2];
    const float* bhe  = (const float*)d_in[3];
    const float* Wdec = (const float*)d_in[4];
    const float* bid  = (const float*)d_in[5];
    const float* bhd  = (const float*)d_in[6];
    const float* Wout = (const float*)d_in[7];
    const float* bout = (const float*)d_in[8];
    float* out = (float*)d_out;

    cudaFuncSetAttribute(fused_encdec, cudaFuncAttributeMaxDynamicSharedMemorySize, SMEM1_TOTAL);

    pack_weights<<<128, 256>>>(Wenc, bie, bhe, Wdec, bid, bhd);
    fused_encdec<<<dim3(10, 2048), THR1, SMEM1_TOTAL>>>(x);
    out_gemm<<<dim3(16, 32), 256>>>(Wout);
    reduce_softmax<<<2048, 40>>>(bout, out);
}